// round 1
// baseline (speedup 1.0000x reference)
#include <cuda_runtime.h>
#include <stdint.h>

// CoarseMatching: conf [N, L, S] fp32, L = h0c*w0c = 4800, S = h1c*w1c = 4800.
// Outputs (concatenated fp32): mconf [N*L], mask_v [N*L], all_j_ids [N*L].
//
// Pass 1: column max per (n, s)  (atomicMax on positive-float bit patterns)
// Pass 2: per-row single scan with two packed 64-bit max reductions:
//   k1 = max over s of  (bits(v) << 32) | (0xFFFFFFFF - s)        -> rowmax
//   k2 = same, restricted to {v > THR, col-valid, bits(v)==colmax} -> candidate
// match iff top32(k2) == top32(k1); index = 0xFFFFFFFF - low32(k2) (first tie).

#define THR  0.2f
#define BRM  2
#define H0   60
#define W0   80
#define H1   60
#define W1   80
#define LSZ  (H0 * W0)   // 4800
#define SSZ  (H1 * W1)   // 4800
#define MAXN 16
#define ROWS_PER_BLOCK 8
#define LCHUNK 100       // 48 chunks cover L = 4800

__device__ unsigned int g_colmax[MAXN * SSZ];

__global__ void init_colmax_kernel(int total) {
    int i = blockIdx.x * blockDim.x + threadIdx.x;
    if (i < total) g_colmax[i] = 0u;
}

__global__ __launch_bounds__(256) void colmax_kernel(const float* __restrict__ conf) {
    const int n  = blockIdx.z;
    const int i4 = blockIdx.x * blockDim.x + threadIdx.x;   // float4 index within a row
    if (i4 >= SSZ / 4) return;
    const int l0 = blockIdx.y * LCHUNK;
    const int l1 = min(l0 + LCHUNK, LSZ);

    const float4* p = reinterpret_cast<const float4*>(
        conf + ((size_t)n * LSZ + (size_t)l0) * SSZ) + i4;

    float4 m = make_float4(0.f, 0.f, 0.f, 0.f);
    const int iters = l1 - l0;
    #pragma unroll 4
    for (int t = 0; t < iters; ++t) {
        float4 v = *p;
        m.x = fmaxf(m.x, v.x);
        m.y = fmaxf(m.y, v.y);
        m.z = fmaxf(m.z, v.z);
        m.w = fmaxf(m.w, v.w);
        p += SSZ / 4;
    }
    unsigned int* cm = g_colmax + (size_t)n * SSZ + (size_t)i4 * 4;
    atomicMax(cm + 0, __float_as_uint(m.x));
    atomicMax(cm + 1, __float_as_uint(m.y));
    atomicMax(cm + 2, __float_as_uint(m.z));
    atomicMax(cm + 3, __float_as_uint(m.w));
}

__device__ __forceinline__ void upd(unsigned long long& k1, unsigned long long& k2,
                                    float v, unsigned cmbits, int s) {
    const unsigned fb = __float_as_uint(v);
    const unsigned long long key =
        ((unsigned long long)fb << 32) | (unsigned long long)(0xFFFFFFFFu - (unsigned)s);
    if (key > k1) k1 = key;
    if (v > THR && fb == cmbits && key > k2) k2 = key;
}

__global__ __launch_bounds__(256) void match_kernel(const float* __restrict__ conf,
                                                    float* __restrict__ out, int N) {
    __shared__ unsigned s_cm[SSZ];                 // 19.2 KB: colmax with invalid cols poisoned
    __shared__ unsigned long long red1[8], red2[8];

    const int tid    = threadIdx.x;
    const int groups = (LSZ + ROWS_PER_BLOCK - 1) / ROWS_PER_BLOCK;
    const int n      = blockIdx.x / groups;
    const int lbase  = (blockIdx.x % groups) * ROWS_PER_BLOCK;
    const int NL     = N * LSZ;

    // Stage column-max row; fold column border-validity by poisoning invalid
    // columns with 0xFFFFFFFF (no conf bit pattern < 1.0f can equal it).
    for (int i = tid; i < SSZ; i += 256) {
        const int sr = i / W1, sc = i % W1;
        const bool v1 = (sr >= BRM) && (sr < H1 - BRM) && (sc >= BRM) && (sc < W1 - BRM);
        s_cm[i] = v1 ? g_colmax[(size_t)n * SSZ + i] : 0xFFFFFFFFu;
    }
    __syncthreads();

    for (int r = 0; r < ROWS_PER_BLOCK; ++r) {
        const int l = lbase + r;
        if (l >= LSZ) break;
        const int o  = n * LSZ + l;
        const int lr = l / W0, lc = l % W0;
        const bool v0 = (lr >= BRM) && (lr < H0 - BRM) && (lc >= BRM) && (lc < W0 - BRM);

        if (!v0) {                                  // uniform per block-row: no divergence
            if (tid == 0) {
                out[o] = 0.f; out[NL + o] = 0.f; out[2 * NL + o] = 0.f;
            }
            continue;
        }

        unsigned long long k1 = 0ull, k2 = 0ull;
        const float4* row = reinterpret_cast<const float4*>(conf + (size_t)o * SSZ);
        const uint4*  cm4 = reinterpret_cast<const uint4*>(s_cm);

        for (int i = tid; i < SSZ / 4; i += 256) {
            const float4 v = row[i];
            const uint4  c = cm4[i];
            const int s = i * 4;
            upd(k1, k2, v.x, c.x, s + 0);
            upd(k1, k2, v.y, c.y, s + 1);
            upd(k1, k2, v.z, c.z, s + 2);
            upd(k1, k2, v.w, c.w, s + 3);
        }

        // warp reduction
        #pragma unroll
        for (int off = 16; off; off >>= 1) {
            unsigned long long o1 = __shfl_down_sync(0xFFFFFFFFu, k1, off);
            unsigned long long o2 = __shfl_down_sync(0xFFFFFFFFu, k2, off);
            if (o1 > k1) k1 = o1;
            if (o2 > k2) k2 = o2;
        }
        const int w = tid >> 5, lane = tid & 31;
        if (lane == 0) { red1[w] = k1; red2[w] = k2; }
        __syncthreads();
        if (tid == 0) {
            #pragma unroll
            for (int w2 = 1; w2 < 8; ++w2) {
                if (red1[w2] > k1) k1 = red1[w2];
                if (red2[w2] > k2) k2 = red2[w2];
            }
            const unsigned rm = (unsigned)(k1 >> 32);
            const bool match = (k2 != 0ull) && ((unsigned)(k2 >> 32) == rm);
            const unsigned j = match ? (0xFFFFFFFFu - (unsigned)(k2 & 0xFFFFFFFFu)) : 0u;
            out[o]          = match ? __uint_as_float(rm) : 0.f;
            out[NL + o]     = match ? 1.f : 0.f;
            out[2 * NL + o] = (float)j;
        }
        __syncthreads();   // protect red1/red2 reuse next row
    }
}

extern "C" void kernel_launch(void* const* d_in, const int* in_sizes, int n_in,
                              void* d_out, int out_size) {
    const float* conf = (const float*)d_in[0];
    const long long total = (long long)in_sizes[0];
    int N = (int)(total / ((long long)LSZ * (long long)SSZ));
    if (N < 1) N = 1;
    if (N > MAXN) N = MAXN;

    // zero colmax scratch (graph-replay safe: re-done every launch)
    init_colmax_kernel<<<(N * SSZ + 255) / 256, 256>>>(N * SSZ);

    // pass 1: column max
    dim3 g1((SSZ / 4 + 255) / 256, (LSZ + LCHUNK - 1) / LCHUNK, N);   // (5, 48, N)
    colmax_kernel<<<g1, 256>>>(conf);

    // pass 2: per-row match
    const int groups = (LSZ + ROWS_PER_BLOCK - 1) / ROWS_PER_BLOCK;   // 600
    match_kernel<<<N * groups, 256>>>(conf, (float*)d_out, N);
}